// round 12
// baseline (speedup 1.0000x reference)
#include <cuda_runtime.h>
#include <cuda_bf16.h>
#include <cstdint>

#define BB 32
#define LL 48
#define NN 325
#define DD 128
#define G3 384
#define WP 385
#define BN (BB*NN)             // 10400 sequences
#define ROWS (BN*LL)           // 499200 gi rows
#define SR 8
#define SP (SR/2)
#define NCREW 2
#define NTHR (NCREW*128)       // 256

typedef unsigned long long ull;

// Scratch for input-side gate projections: gi[t][l][g], row r = t*LL+l.
// Biases b_ih (+ b_hh for gates r,z) are folded in here.
__device__ float g_gi[(size_t)ROWS * G3];

// ===================== SIMT helpers (gi kernel) ============================
__device__ __forceinline__ ull pk2(float lo, float hi) {
    ull r; asm("mov.b64 %0, {%1, %2};" : "=l"(r) : "f"(lo), "f"(hi)); return r;
}
__device__ __forceinline__ void upk2(ull v, float& lo, float& hi) {
    asm("mov.b64 {%0, %1}, %2;" : "=f"(lo), "=f"(hi) : "l"(v));
}
__device__ __forceinline__ void fma2(ull& d, ull a, ull b) {
    asm("fma.rn.f32x2 %0, %1, %2, %0;" : "+l"(d) : "l"(a), "l"(b));
}
__device__ __forceinline__ float sigm(float x)  { return 1.f / (1.f + __expf(-x)); }
__device__ __forceinline__ float tanh_(float x) { return 1.f - 2.f / (__expf(2.f*x) + 1.f); }

__device__ __forceinline__ void dot128(
    const float* __restrict__ Wt, const float* __restrict__ stage, int j,
    ull acc0[SP], ull acc1[SP], ull acc2[SP])
{
    #pragma unroll 8
    for (int k = 0; k < DD; ++k) {
        const float* wr = Wt + k*WP;
        float w0 = wr[j], w1 = wr[j+DD], w2 = wr[j+2*DD];
        ull W0 = pk2(w0, w0), W1 = pk2(w1, w1), W2 = pk2(w2, w2);
        const ulonglong2* hp = (const ulonglong2*)(stage + k*SR);
        ulonglong2 va = hp[0], vb = hp[1];
        fma2(acc0[0], W0, va.x); fma2(acc1[0], W1, va.x); fma2(acc2[0], W2, va.x);
        fma2(acc0[1], W0, va.y); fma2(acc1[1], W1, va.y); fma2(acc2[1], W2, va.y);
        fma2(acc0[2], W0, vb.x); fma2(acc1[2], W1, vb.x); fma2(acc2[2], W2, vb.x);
        fma2(acc0[3], W0, vb.y); fma2(acc1[3], W1, vb.y); fma2(acc2[3], W2, vb.y);
    }
}

// ---------------------------------------------------------------------------
// Kernel 1 (proven): gi[r][g] = x_row(r).W_ih[g,:] + bias[g]
// bias = b_ih + b_hh for gates r,z (they sit outside r*(.)), b_ih only for n.
// ---------------------------------------------------------------------------
__global__ void __launch_bounds__(NTHR, 1) gi_kernel(
    const float* __restrict__ X, const float* __restrict__ W_ih,
    const float* __restrict__ b_ih, const float* __restrict__ b_hh)
{
    extern __shared__ float sm[];
    float* Wt = sm;
    float* xs = sm + DD*WP;
    const int tid = threadIdx.x;
    for (int i = tid; i < DD*G3; i += NTHR) {
        int g = i / DD, k = i - g*DD;
        Wt[k*WP + g] = W_ih[i];
    }
    const int crew = tid >> 7;
    const int j    = tid & 127;
    float* myxs = xs + crew * (DD*SR);
    const float b0 = b_ih[j]      + b_hh[j];
    const float b1 = b_ih[j+DD]   + b_hh[j+DD];
    const float b2 = b_ih[j+2*DD];
    __syncthreads();

    const int ngroups = ROWS / SR;
    for (int grp = blockIdx.x*NCREW + crew; grp < ngroups; grp += (int)gridDim.x*NCREW) {
        const int r0 = grp * SR;
        #pragma unroll
        for (int s = 0; s < SR; ++s) {
            int r = r0 + s;
            int t = r / LL, l = r - t*LL;
            int b = t / NN, n = t - b*NN;
            myxs[j*SR + s] = X[(((size_t)(b*LL + l))*NN + n)*DD + j];
        }
        __syncthreads();

        ull acc0[SP], acc1[SP], acc2[SP];
        #pragma unroll
        for (int p = 0; p < SP; ++p) {
            acc0[p] = pk2(b0, b0); acc1[p] = pk2(b1, b1); acc2[p] = pk2(b2, b2);
        }
        dot128(Wt, myxs, j, acc0, acc1, acc2);

        #pragma unroll
        for (int p = 0; p < SP; ++p) {
            float a, c;
            size_t base0 = (size_t)(r0 + 2*p)     * G3;
            size_t base1 = (size_t)(r0 + 2*p + 1) * G3;
            upk2(acc0[p], a, c); g_gi[base0 + j]        = a; g_gi[base1 + j]        = c;
            upk2(acc1[p], a, c); g_gi[base0 + DD + j]   = a; g_gi[base1 + DD + j]   = c;
            upk2(acc2[p], a, c); g_gi[base0 + 2*DD + j] = a; g_gi[base1 + 2*DD + j] = c;
        }
        __syncthreads();
    }
}

// ===================== mma.sync machinery (base ISA, sm_80+) ===============
__device__ __forceinline__ uint32_t smem_u32(const void* p) {
    uint32_t a;
    asm("{ .reg .u64 t; cvta.to.shared.u64 t, %1; cvt.u32.u64 %0, t; }" : "=r"(a) : "l"(p));
    return a;
}
#define MMA_BF16(c, a, b0_, b1_) \
    asm volatile("mma.sync.aligned.m16n8k16.row.col.f32.bf16.bf16.f32 " \
        "{%0,%1,%2,%3}, {%4,%5,%6,%7}, {%8,%9}, {%0,%1,%2,%3};" \
        : "+f"((c)[0]), "+f"((c)[1]), "+f"((c)[2]), "+f"((c)[3]) \
        : "r"((a)[0]), "r"((a)[1]), "r"((a)[2]), "r"((a)[3]), "r"(b0_), "r"(b1_))

#define LDSM4(r, addr) \
    asm volatile("ldmatrix.sync.aligned.m8n8.x4.shared.b16 {%0,%1,%2,%3}, [%4];" \
        : "=r"((r)[0]), "=r"((r)[1]), "=r"((r)[2]), "=r"((r)[3]) : "r"(addr))

__device__ __forceinline__ uint32_t pbf2(float x, float y) {
    __nv_bfloat162 t = __floats2bfloat162_rn(x, y);
    return *(uint32_t*)&t;
}
__device__ __forceinline__ float2 ubf2(uint32_t u) {
    __nv_bfloat162 t = *(__nv_bfloat162*)&u;
    return make_float2(__bfloat162float(t.x), __bfloat162float(t.y));
}

// Shared layout for gru_mma (bytes). W pitch 136 bf16 = 272B = 17x16B units
// -> the 8 row-pointers of every ldmatrix hit distinct 16B banks (17 odd).
#define WPITCH 136
#define WS_LO  (G3*WPITCH*2)          // 104448: lo tile after hi tile
#define BN_OFF (2*G3*WPITCH*2)        // 208896
#define SMEM_GRU (BN_OFF + 512 + 128)

// ---------------------------------------------------------------------------
// Kernel 2: GRU recurrence via mma.sync bf16x3. 82 CTAs x 128 seqs, 8 warps.
// Warp w owns M-rows [16w,16w+16) forever; h lives ONLY in A-fragment regs
// (C-frag layout == A-frag layout for m16n8k16). W_hh hi/lo in shared with
// columns reordered col' = s*24 + gate*8 + (j%8). No syncthreads in the loop.
// ---------------------------------------------------------------------------
__global__ void __launch_bounds__(256, 1) gru_mma(
    const float* __restrict__ W_hh, const float* __restrict__ b_hh,
    float* __restrict__ out)
{
    extern __shared__ unsigned char smem[];
    __nv_bfloat16* wh = (__nv_bfloat16*)(smem);
    __nv_bfloat16* wl = (__nv_bfloat16*)(smem + WS_LO);
    float* bnsh = (float*)(smem + BN_OFF);
    const int tid = threadIdx.x, wid = tid >> 5, lane = tid & 31;

    // Load + split + column-reorder W_hh.
    for (int i = tid; i < G3*DD; i += 256) {
        int n = i >> 7, k = i & 127;
        float w = W_hh[i];
        __nv_bfloat16 hb = __float2bfloat16(w);
        __nv_bfloat16 lb = __float2bfloat16(w - __bfloat162float(hb));
        int g = n >> 7, j = n & 127;
        int colp = (j >> 3)*24 + g*8 + (j & 7);
        wh[colp*WPITCH + k] = hb;
        wl[colp*WPITCH + k] = lb;
    }
    for (int i = tid; i < DD; i += 256) bnsh[i] = b_hh[2*DD + i];
    __syncthreads();

    const int qr = lane >> 2, qc = lane & 3;
    const int r0 = blockIdx.x*128 + wid*16 + qr;   // global sequence ids
    const int r1 = r0 + 8;
    const bool v0 = (r0 < BN), v1 = (r1 < BN);
    const int brow = lane & 7, bko = (lane >> 3) << 3;
    const uint32_t sb = smem_u32(smem);

    // A fragments (h as bf16 hi/lo), current + next step. Zero init (h0=0).
    uint32_t ah[8][4], al[8][4], nh[8][4], nl[8][4];
    #pragma unroll
    for (int kc = 0; kc < 8; ++kc)
        #pragma unroll
        for (int q = 0; q < 4; ++q) { ah[kc][q] = 0u; al[kc][q] = 0u; }

    for (int l = 0; l < LL; ++l) {
        const float* gb0 = g_gi + ((size_t)r0*LL + l)*G3;
        const float* gb1 = g_gi + ((size_t)r1*LL + l)*G3;

        #pragma unroll
        for (int s = 0; s < 16; ++s) {
            const int j0 = 8*s + 2*qc;
            // gi prefetch (issued early; hidden behind the mma block)
            float2 i0r = make_float2(0.f,0.f), i0z = i0r, i0n = i0r;
            float2 i1r = i0r, i1z = i0r, i1n = i0r;
            if (v0) {
                i0r = *(const float2*)(gb0 + j0);
                i0z = *(const float2*)(gb0 + DD + j0);
                i0n = *(const float2*)(gb0 + 2*DD + j0);
            }
            if (v1) {
                i1r = *(const float2*)(gb1 + j0);
                i1z = *(const float2*)(gb1 + DD + j0);
                i1n = *(const float2*)(gb1 + 2*DD + j0);
            }
            float2 bnv = *(const float2*)(bnsh + j0);

            float acc[3][4];
            #pragma unroll
            for (int g = 0; g < 3; ++g)
                #pragma unroll
                for (int q = 0; q < 4; ++q) acc[g][q] = 0.f;

            const int nb = s*24;
            #pragma unroll
            for (int kc2 = 0; kc2 < 4; ++kc2) {
                uint32_t bh[3][4], bl[3][4];
                #pragma unroll
                for (int g = 0; g < 3; ++g) {
                    uint32_t ab = sb + (uint32_t)(((nb + 8*g + brow)*WPITCH + 32*kc2 + bko) << 1);
                    LDSM4(bh[g], ab);
                    LDSM4(bl[g], ab + WS_LO);
                }
                // 18 mma, same-acc distance 3 for latency cover
                #pragma unroll
                for (int g = 0; g < 3; ++g) MMA_BF16(acc[g], ah[2*kc2],   bh[g][0], bh[g][1]);
                #pragma unroll
                for (int g = 0; g < 3; ++g) MMA_BF16(acc[g], ah[2*kc2+1], bh[g][2], bh[g][3]);
                #pragma unroll
                for (int g = 0; g < 3; ++g) MMA_BF16(acc[g], al[2*kc2],   bh[g][0], bh[g][1]);
                #pragma unroll
                for (int g = 0; g < 3; ++g) MMA_BF16(acc[g], al[2*kc2+1], bh[g][2], bh[g][3]);
                #pragma unroll
                for (int g = 0; g < 3; ++g) MMA_BF16(acc[g], ah[2*kc2],   bl[g][0], bl[g][1]);
                #pragma unroll
                for (int g = 0; g < 3; ++g) MMA_BF16(acc[g], ah[2*kc2+1], bl[g][2], bl[g][3]);
            }

            // Epilogue. C-frag: [0]=(row0,j0) [1]=(row0,j0+1) [2]=(row1,j0) [3]=(row1,j0+1)
            const int kc = s >> 1;
            const int e  = (s & 1) << 1;           // frag reg pair for this k-half
            float2 hH0 = ubf2(ah[kc][e+0]), hL0 = ubf2(al[kc][e+0]);   // row0 old h
            float2 hH1 = ubf2(ah[kc][e+1]), hL1 = ubf2(al[kc][e+1]);   // row1 old h

            float rr, zz, ng;
            rr = sigm(i0r.x + acc[0][0]); zz = sigm(i0z.x + acc[1][0]);
            ng = tanh_(i0n.x + rr*(acc[2][0] + bnv.x));
            float h0x = (1.f - zz)*ng + zz*(hH0.x + hL0.x);
            rr = sigm(i0r.y + acc[0][1]); zz = sigm(i0z.y + acc[1][1]);
            ng = tanh_(i0n.y + rr*(acc[2][1] + bnv.y));
            float h0y = (1.f - zz)*ng + zz*(hH0.y + hL0.y);
            rr = sigm(i1r.x + acc[0][2]); zz = sigm(i1z.x + acc[1][2]);
            ng = tanh_(i1n.x + rr*(acc[2][2] + bnv.x));
            float h1x = (1.f - zz)*ng + zz*(hH1.x + hL1.x);
            rr = sigm(i1r.y + acc[0][3]); zz = sigm(i1z.y + acc[1][3]);
            ng = tanh_(i1n.y + rr*(acc[2][3] + bnv.y));
            float h1y = (1.f - zz)*ng + zz*(hH1.y + hL1.y);

            if (v0) *(float2*)(out + ((size_t)l*BN + r0)*DD + j0) = make_float2(h0x, h0y);
            if (v1) *(float2*)(out + ((size_t)l*BN + r1)*DD + j0) = make_float2(h1x, h1y);

            // Pack new h (hi + residual lo) straight into next-step A frags.
            uint32_t H0 = pbf2(h0x, h0y); float2 c0 = ubf2(H0);
            uint32_t L0 = pbf2(h0x - c0.x, h0y - c0.y);
            uint32_t H1 = pbf2(h1x, h1y); float2 c1 = ubf2(H1);
            uint32_t L1 = pbf2(h1x - c1.x, h1y - c1.y);
            nh[kc][e+0] = H0; nl[kc][e+0] = L0;
            nh[kc][e+1] = H1; nl[kc][e+1] = L1;
        }

        // Swap: next-step fragments become current.
        #pragma unroll
        for (int kc = 0; kc < 8; ++kc)
            #pragma unroll
            for (int q = 0; q < 4; ++q) { ah[kc][q] = nh[kc][q]; al[kc][q] = nl[kc][q]; }
    }
}

extern "C" void kernel_launch(void* const* d_in, const int* in_sizes, int n_in,
                              void* d_out, int out_size)
{
    const float* X    = (const float*)d_in[0];
    const float* W_ih = (const float*)d_in[1];
    const float* W_hh = (const float*)d_in[2];
    const float* b_ih = (const float*)d_in[3];
    const float* b_hh = (const float*)d_in[4];
    float* out = (float*)d_out;

    const int smem_gi = (DD*WP + NCREW*DD*SR) * (int)sizeof(float);   // 201216 B
    cudaFuncSetAttribute(gi_kernel, cudaFuncAttributeMaxDynamicSharedMemorySize, smem_gi);
    cudaFuncSetAttribute(gru_mma,   cudaFuncAttributeMaxDynamicSharedMemorySize, SMEM_GRU);

    gi_kernel<<<148, NTHR, smem_gi>>>(X, W_ih, b_ih, b_hh);
    gru_mma<<<(BN + 127)/128, 256, SMEM_GRU>>>(W_hh, b_hh, out);      // 82 CTAs
}

// round 14
// speedup vs baseline: 2.1770x; 2.1770x over previous
#include <cuda_runtime.h>
#include <cuda_bf16.h>
#include <cstdint>

#define BB 32
#define LL 48
#define NN 325
#define DD 128
#define G3 384
#define WP 385
#define BN (BB*NN)             // 10400 sequences
#define ROWS (BN*LL)           // 499200 gi rows
#define SR 8
#define SP (SR/2)
#define NCREW 2
#define NTHR (NCREW*128)       // 256

typedef unsigned long long ull;

// Scratch for input-side gate projections: gi[t][l][g], row r = t*LL+l.
// b_ih folded in here; gru adds b_hh itself.
__device__ float g_gi[(size_t)ROWS * G3];

// ===================== common helpers ======================================
__device__ __forceinline__ ull pk2(float lo, float hi) {
    ull r; asm("mov.b64 %0, {%1, %2};" : "=l"(r) : "f"(lo), "f"(hi)); return r;
}
__device__ __forceinline__ void upk2(ull v, float& lo, float& hi) {
    asm("mov.b64 {%0, %1}, %2;" : "=f"(lo), "=f"(hi) : "l"(v));
}
__device__ __forceinline__ void fma2(ull& d, ull a, ull b) {
    asm("fma.rn.f32x2 %0, %1, %2, %0;" : "+l"(d) : "l"(a), "l"(b));
}
__device__ __forceinline__ float sigm(float x)  { return 1.f / (1.f + __expf(-x)); }
__device__ __forceinline__ float tanh_(float x) { return 1.f - 2.f / (__expf(2.f*x) + 1.f); }

__device__ __forceinline__ uint32_t smem_u32(const void* p) {
    uint32_t a;
    asm("{ .reg .u64 t; cvta.to.shared.u64 t, %1; cvt.u32.u64 %0, t; }" : "=r"(a) : "l"(p));
    return a;
}
#define MMA_BF16(c, a, b0_, b1_) \
    asm volatile("mma.sync.aligned.m16n8k16.row.col.f32.bf16.bf16.f32 " \
        "{%0,%1,%2,%3}, {%4,%5,%6,%7}, {%8,%9}, {%0,%1,%2,%3};" \
        : "+f"((c)[0]), "+f"((c)[1]), "+f"((c)[2]), "+f"((c)[3]) \
        : "r"((a)[0]), "r"((a)[1]), "r"((a)[2]), "r"((a)[3]), "r"(b0_), "r"(b1_))

#define LDSM4(r, addr) \
    asm volatile("ldmatrix.sync.aligned.m8n8.x4.shared.b16 {%0,%1,%2,%3}, [%4];" \
        : "=r"((r)[0]), "=r"((r)[1]), "=r"((r)[2]), "=r"((r)[3]) : "r"(addr))

__device__ __forceinline__ uint32_t pbf2(float x, float y) {
    __nv_bfloat162 t = __floats2bfloat162_rn(x, y);
    return *(uint32_t*)&t;
}
__device__ __forceinline__ float2 ubf2(uint32_t u) {
    __nv_bfloat162 t = *(__nv_bfloat162*)&u;
    return make_float2(__bfloat162float(t.x), __bfloat162float(t.y));
}

// gi_mma shared layout: W pitch 136 bf16 (=272B = 17x16B -> ldmatrix rows hit
// distinct banks). Natural column order colp = g*128+j.
#define WPITCH 136
#define WS_LO  (G3*WPITCH*2)          // 104448
#define BI_OFF (2*G3*WPITCH*2)        // 208896
#define SMEM_GIMMA (BI_OFF + 1536 + 64)

// ---------------------------------------------------------------------------
// Kernel 1 (NEW): gi via mma.sync bf16x3. 148 CTAs x 8 warps; each warp owns
// independent 16-row output tiles (rows = consecutive r in g_gi order).
// A fragments built in registers straight from X (fp32->bf16 hi/lo split);
// W_ih hi/lo in smem. 48 n-tiles per tile, in 8 batches of 6 concurrent
// accumulators (acc chains spaced 6 issues -> no HMMA-latency stall).
// ---------------------------------------------------------------------------
__global__ void __launch_bounds__(256, 1) gi_mma(
    const float* __restrict__ X, const float* __restrict__ W_ih,
    const float* __restrict__ b_ih)
{
    extern __shared__ unsigned char smem[];
    __nv_bfloat16* wh = (__nv_bfloat16*)(smem);
    __nv_bfloat16* wl = (__nv_bfloat16*)(smem + WS_LO);
    float* bsh = (float*)(smem + BI_OFF);
    const int tid = threadIdx.x, wid = tid >> 5, lane = tid & 31;

    // Load + bf16-split W_ih: wh/wl[col][k], col = g*128+j (natural).
    for (int i = tid; i < G3*DD; i += 256) {
        int col = i >> 7, k = i & 127;
        float w = W_ih[i];
        __nv_bfloat16 hb = __float2bfloat16(w);
        __nv_bfloat16 lb = __float2bfloat16(w - __bfloat162float(hb));
        wh[col*WPITCH + k] = hb;
        wl[col*WPITCH + k] = lb;
    }
    for (int i = tid; i < G3; i += 256) bsh[i] = b_ih[i];
    __syncthreads();

    const int qr = lane >> 2, qc = lane & 3;
    const int brow = lane & 7, bko = (lane >> 3) << 3;
    const uint32_t sb = smem_u32(smem);

    const int NT = ROWS / 16;              // 31200 row-tiles
    const int wg = blockIdx.x*8 + wid;     // 0..1183
    for (int rt = wg; rt < NT; rt += 148*8) {
        // Rows r0 (=rt*16+qr) and r1 (=r0+8) for this thread.
        const int r0 = rt*16 + qr;
        const int r1 = r0 + 8;
        int t0 = r0 / LL, l0 = r0 - t0*LL;
        int t1 = r1 / LL, l1 = r1 - t1*LL;
        int b0i = t0 / NN, n0 = t0 - b0i*NN;
        int b1i = t1 / NN, n1 = t1 - b1i*NN;
        const float* px0 = X + ((size_t)(b0i*LL + l0)*NN + n0)*DD;
        const float* px1 = X + ((size_t)(b1i*LL + l1)*NN + n1)*DD;

        // Build A fragments (proven layout: {kLo(r0), kLo(r1), kHi(r0), kHi(r1)}).
        uint32_t ah[8][4], al[8][4];
        #pragma unroll
        for (int kc = 0; kc < 8; ++kc) {
            float2 xa = *(const float2*)(px0 + 16*kc + 2*qc);
            float2 xb = *(const float2*)(px1 + 16*kc + 2*qc);
            float2 xc = *(const float2*)(px0 + 16*kc + 8 + 2*qc);
            float2 xd = *(const float2*)(px1 + 16*kc + 8 + 2*qc);
            uint32_t H;
            H = pbf2(xa.x, xa.y); ah[kc][0] = H; { float2 c = ubf2(H); al[kc][0] = pbf2(xa.x - c.x, xa.y - c.y); }
            H = pbf2(xb.x, xb.y); ah[kc][1] = H; { float2 c = ubf2(H); al[kc][1] = pbf2(xb.x - c.x, xb.y - c.y); }
            H = pbf2(xc.x, xc.y); ah[kc][2] = H; { float2 c = ubf2(H); al[kc][2] = pbf2(xc.x - c.x, xc.y - c.y); }
            H = pbf2(xd.x, xd.y); ah[kc][3] = H; { float2 c = ubf2(H); al[kc][3] = pbf2(xd.x - c.x, xd.y - c.y); }
        }

        // 48 n-tiles in 8 batches of 6 concurrent accumulators.
        #pragma unroll 1
        for (int nb = 0; nb < 8; ++nb) {
            float acc[6][4];
            #pragma unroll
            for (int u = 0; u < 6; ++u)
                #pragma unroll
                for (int q = 0; q < 4; ++q) acc[u][q] = 0.f;

            #pragma unroll
            for (int kc2 = 0; kc2 < 4; ++kc2) {
                uint32_t bh[6][4], bl[6][4];
                #pragma unroll
                for (int u = 0; u < 6; ++u) {
                    uint32_t ab = sb + (uint32_t)((((nb*6 + u)*8 + brow)*WPITCH + 32*kc2 + bko) << 1);
                    LDSM4(bh[u], ab);
                    LDSM4(bl[u], ab + WS_LO);
                }
                // 36 mma, each acc revisited every 6 issues.
                #pragma unroll
                for (int u = 0; u < 6; ++u) MMA_BF16(acc[u], ah[2*kc2],   bh[u][0], bh[u][1]);
                #pragma unroll
                for (int u = 0; u < 6; ++u) MMA_BF16(acc[u], ah[2*kc2+1], bh[u][2], bh[u][3]);
                #pragma unroll
                for (int u = 0; u < 6; ++u) MMA_BF16(acc[u], al[2*kc2],   bh[u][0], bh[u][1]);
                #pragma unroll
                for (int u = 0; u < 6; ++u) MMA_BF16(acc[u], al[2*kc2+1], bh[u][2], bh[u][3]);
                #pragma unroll
                for (int u = 0; u < 6; ++u) MMA_BF16(acc[u], ah[2*kc2],   bl[u][0], bl[u][1]);
                #pragma unroll
                for (int u = 0; u < 6; ++u) MMA_BF16(acc[u], ah[2*kc2+1], bl[u][2], bl[u][3]);
            }

            // Epilogue: add bias, store. C-frag: [0]=(r0,c) [1]=(r0,c+1) [2]=(r1,c) [3]=(r1,c+1).
            #pragma unroll
            for (int u = 0; u < 6; ++u) {
                const int c0 = (nb*6 + u)*8 + 2*qc;
                float2 bi = *(const float2*)(bsh + c0);
                *(float2*)(g_gi + (size_t)r0*G3 + c0) = make_float2(acc[u][0] + bi.x, acc[u][1] + bi.y);
                *(float2*)(g_gi + (size_t)r1*G3 + c0) = make_float2(acc[u][2] + bi.x, acc[u][3] + bi.y);
            }
        }
    }
}

// ---------------------------------------------------------------------------
// Kernel 2 (R8 SIMT, proven 1567us): GRU recurrence. 650 blocks x 2 crews x
// 8 seqs, 48 steps in-block, h double-buffered, 1 barrier/step.
// ---------------------------------------------------------------------------
__device__ __forceinline__ void dot128(
    const float* __restrict__ Wt, const float* __restrict__ stage, int j,
    ull acc0[SP], ull acc1[SP], ull acc2[SP])
{
    #pragma unroll 8
    for (int k = 0; k < DD; ++k) {
        const float* wr = Wt + k*WP;
        float w0 = wr[j], w1 = wr[j+DD], w2 = wr[j+2*DD];
        ull W0 = pk2(w0, w0), W1 = pk2(w1, w1), W2 = pk2(w2, w2);
        const ulonglong2* hp = (const ulonglong2*)(stage + k*SR);
        ulonglong2 va = hp[0], vb = hp[1];
        fma2(acc0[0], W0, va.x); fma2(acc1[0], W1, va.x); fma2(acc2[0], W2, va.x);
        fma2(acc0[1], W0, va.y); fma2(acc1[1], W1, va.y); fma2(acc2[1], W2, va.y);
        fma2(acc0[2], W0, vb.x); fma2(acc1[2], W1, vb.x); fma2(acc2[2], W2, vb.x);
        fma2(acc0[3], W0, vb.y); fma2(acc1[3], W1, vb.y); fma2(acc2[3], W2, vb.y);
    }
}

__global__ void __launch_bounds__(NTHR, 1) gru_kernel(
    const float* __restrict__ W_hh, const float* __restrict__ b_hh,
    float* __restrict__ out)
{
    extern __shared__ float sm[];
    float* Wt = sm;                      // [DD][WP]  W_hh^T
    float* hs = sm + DD*WP;              // [NCREW][2 bufs][DD][SR]
    const int tid = threadIdx.x;
    for (int i = tid; i < DD*G3; i += NTHR) {
        int g = i / DD, k = i - g*DD;
        Wt[k*WP + g] = W_hh[i];
    }
    const int crew = tid >> 7;
    const int j    = tid & 127;
    float* buf0 = hs + crew * (2*DD*SR);
    float* buf1 = buf0 + DD*SR;
    const float b0 = b_hh[j], b1 = b_hh[j+DD], b2 = b_hh[j+2*DD];
    const int t0 = (blockIdx.x*NCREW + crew) * SR;

    float hreg[SR];
    #pragma unroll
    for (int s = 0; s < SR; ++s) { hreg[s] = 0.f; buf0[j*SR + s] = 0.f; }
    __syncthreads();

    for (int l = 0; l < LL; ++l) {
        float* cur = (l & 1) ? buf1 : buf0;
        float* nxt = (l & 1) ? buf0 : buf1;

        float gir[SR], giz[SR], gin[SR];
        #pragma unroll
        for (int s = 0; s < SR; ++s) {
            const float* gp = g_gi + ((size_t)(t0 + s)*LL + l)*G3;
            gir[s] = gp[j]; giz[s] = gp[j+DD]; gin[s] = gp[j+2*DD];
        }

        ull acc0[SP], acc1[SP], acc2[SP];
        #pragma unroll
        for (int p = 0; p < SP; ++p) {
            acc0[p] = pk2(b0, b0); acc1[p] = pk2(b1, b1); acc2[p] = pk2(b2, b2);
        }
        dot128(Wt, cur, j, acc0, acc1, acc2);

        #pragma unroll
        for (int p = 0; p < SP; ++p) {
            float hr0, hr1, hz0, hz1, hn0, hn1;
            upk2(acc0[p], hr0, hr1);
            upk2(acc1[p], hz0, hz1);
            upk2(acc2[p], hn0, hn1);
            {
                int s = 2*p;
                float r  = sigm(gir[s] + hr0);
                float z  = sigm(giz[s] + hz0);
                float ng = tanh_(gin[s] + r*hn0);
                hreg[s]  = (1.f - z)*ng + z*hreg[s];
            }
            {
                int s = 2*p + 1;
                float r  = sigm(gir[s] + hr1);
                float z  = sigm(giz[s] + hz1);
                float ng = tanh_(gin[s] + r*hn1);
                hreg[s]  = (1.f - z)*ng + z*hreg[s];
            }
        }
        float4* hp4 = (float4*)(nxt + j*SR);
        hp4[0] = make_float4(hreg[0], hreg[1], hreg[2], hreg[3]);
        hp4[1] = make_float4(hreg[4], hreg[5], hreg[6], hreg[7]);
        #pragma unroll
        for (int s = 0; s < SR; ++s)
            out[((size_t)l*BN + (t0 + s))*DD + j] = hreg[s];
        __syncthreads();
    }
}

extern "C" void kernel_launch(void* const* d_in, const int* in_sizes, int n_in,
                              void* d_out, int out_size)
{
    const float* X    = (const float*)d_in[0];
    const float* W_ih = (const float*)d_in[1];
    const float* W_hh = (const float*)d_in[2];
    const float* b_ih = (const float*)d_in[3];
    const float* b_hh = (const float*)d_in[4];
    float* out = (float*)d_out;

    const int smem_gru = (DD*WP + NCREW*2*DD*SR) * (int)sizeof(float);  // 213504 B
    cudaFuncSetAttribute(gi_mma,     cudaFuncAttributeMaxDynamicSharedMemorySize, SMEM_GIMMA);
    cudaFuncSetAttribute(gru_kernel, cudaFuncAttributeMaxDynamicSharedMemorySize, smem_gru);

    gi_mma<<<148, 256, SMEM_GIMMA>>>(X, W_ih, b_ih);
    gru_kernel<<<BN/(NCREW*SR), NTHR, smem_gru>>>(W_hh, b_hh, out);   // 650 blocks
}

// round 15
// speedup vs baseline: 2.8169x; 1.2939x over previous
#include <cuda_runtime.h>
#include <cuda_bf16.h>
#include <cstdint>

#define BB 32
#define LL 48
#define NN 325
#define DD 128
#define G3 384
#define BN (BB*NN)             // 10400 sequences
#define ROWS (BN*LL)           // 499200 gi rows

typedef unsigned long long ull;

// Scratch for input-side gate projections: gi[t][l][g], row r = t*LL+l.
// Folded bias: b_ih + b_hh for gates r,z; b_ih only for gate n.
__device__ float g_gi[(size_t)ROWS * G3];

// ===================== common helpers ======================================
__device__ __forceinline__ float sigm(float x)  { return 1.f / (1.f + __expf(-x)); }
__device__ __forceinline__ float tanh_(float x) { return 1.f - 2.f / (__expf(2.f*x) + 1.f); }

__device__ __forceinline__ uint32_t smem_u32(const void* p) {
    uint32_t a;
    asm("{ .reg .u64 t; cvta.to.shared.u64 t, %1; cvt.u32.u64 %0, t; }" : "=r"(a) : "l"(p));
    return a;
}
#define MMA_BF16(c, a, b0_, b1_) \
    asm volatile("mma.sync.aligned.m16n8k16.row.col.f32.bf16.bf16.f32 " \
        "{%0,%1,%2,%3}, {%4,%5,%6,%7}, {%8,%9}, {%0,%1,%2,%3};" \
        : "+f"((c)[0]), "+f"((c)[1]), "+f"((c)[2]), "+f"((c)[3]) \
        : "r"((a)[0]), "r"((a)[1]), "r"((a)[2]), "r"((a)[3]), "r"(b0_), "r"(b1_))

#define LDSM4(r, addr) \
    asm volatile("ldmatrix.sync.aligned.m8n8.x4.shared.b16 {%0,%1,%2,%3}, [%4];" \
        : "=r"((r)[0]), "=r"((r)[1]), "=r"((r)[2]), "=r"((r)[3]) : "r"(addr))

__device__ __forceinline__ uint32_t pbf2(float x, float y) {
    __nv_bfloat162 t = __floats2bfloat162_rn(x, y);
    return *(uint32_t*)&t;
}
__device__ __forceinline__ float2 ubf2(uint32_t u) {
    __nv_bfloat162 t = *(__nv_bfloat162*)&u;
    return make_float2(__bfloat162float(t.x), __bfloat162float(t.y));
}

// W tiles in shared: pitch 136 bf16 (=272B = 17x16B -> ldmatrix row pointers
// hit distinct 16B banks).
#define WPITCH 136
#define WS_LO  (G3*WPITCH*2)          // 104448

// gi_mma layout
#define BI_OFF (2*G3*WPITCH*2)        // 208896
#define SMEM_GIMMA (BI_OFF + 1536 + 64)

// gru_mma layout
#define HP 130                         // h-buffer pitch (floats): row stride 520B, conflict-free
#define HB_OFF (2*G3*WPITCH*2)        // 208896
#define BN_OFF (HB_OFF + 16*HP*4)     // + 8320 = 217216
#define SMEM_GRUMMA (BN_OFF + 512 + 64)

// ---------------------------------------------------------------------------
// Kernel 1 (proven R13): gi via mma.sync bf16x3. 148 CTAs x 8 warps.
// Bias fold: r,z get b_ih+b_hh; n gets b_ih.
// ---------------------------------------------------------------------------
__global__ void __launch_bounds__(256, 1) gi_mma(
    const float* __restrict__ X, const float* __restrict__ W_ih,
    const float* __restrict__ b_ih, const float* __restrict__ b_hh)
{
    extern __shared__ unsigned char smem[];
    __nv_bfloat16* wh = (__nv_bfloat16*)(smem);
    __nv_bfloat16* wl = (__nv_bfloat16*)(smem + WS_LO);
    float* bsh = (float*)(smem + BI_OFF);
    const int tid = threadIdx.x, wid = tid >> 5, lane = tid & 31;

    for (int i = tid; i < G3*DD; i += 256) {
        int col = i >> 7, k = i & 127;
        float w = W_ih[i];
        __nv_bfloat16 hb = __float2bfloat16(w);
        __nv_bfloat16 lb = __float2bfloat16(w - __bfloat162float(hb));
        wh[col*WPITCH + k] = hb;
        wl[col*WPITCH + k] = lb;
    }
    for (int i = tid; i < G3; i += 256)
        bsh[i] = b_ih[i] + (i < 2*DD ? b_hh[i] : 0.f);
    __syncthreads();

    const int qr = lane >> 2, qc = lane & 3;
    const int brow = lane & 7, bko = (lane >> 3) << 3;
    const uint32_t sb = smem_u32(smem);

    const int NT = ROWS / 16;              // 31200 row-tiles
    const int wg = blockIdx.x*8 + wid;
    for (int rt = wg; rt < NT; rt += 148*8) {
        const int r0 = rt*16 + qr;
        const int r1 = r0 + 8;
        int t0 = r0 / LL, l0 = r0 - t0*LL;
        int t1 = r1 / LL, l1 = r1 - t1*LL;
        int b0i = t0 / NN, n0 = t0 - b0i*NN;
        int b1i = t1 / NN, n1 = t1 - b1i*NN;
        const float* px0 = X + ((size_t)(b0i*LL + l0)*NN + n0)*DD;
        const float* px1 = X + ((size_t)(b1i*LL + l1)*NN + n1)*DD;

        uint32_t ah[8][4], al[8][4];
        #pragma unroll
        for (int kc = 0; kc < 8; ++kc) {
            float2 xa = *(const float2*)(px0 + 16*kc + 2*qc);
            float2 xb = *(const float2*)(px1 + 16*kc + 2*qc);
            float2 xc = *(const float2*)(px0 + 16*kc + 8 + 2*qc);
            float2 xd = *(const float2*)(px1 + 16*kc + 8 + 2*qc);
            uint32_t H;
            H = pbf2(xa.x, xa.y); ah[kc][0] = H; { float2 c = ubf2(H); al[kc][0] = pbf2(xa.x - c.x, xa.y - c.y); }
            H = pbf2(xb.x, xb.y); ah[kc][1] = H; { float2 c = ubf2(H); al[kc][1] = pbf2(xb.x - c.x, xb.y - c.y); }
            H = pbf2(xc.x, xc.y); ah[kc][2] = H; { float2 c = ubf2(H); al[kc][2] = pbf2(xc.x - c.x, xc.y - c.y); }
            H = pbf2(xd.x, xd.y); ah[kc][3] = H; { float2 c = ubf2(H); al[kc][3] = pbf2(xd.x - c.x, xd.y - c.y); }
        }

        #pragma unroll 1
        for (int nb = 0; nb < 8; ++nb) {
            float acc[6][4];
            #pragma unroll
            for (int u = 0; u < 6; ++u)
                #pragma unroll
                for (int q = 0; q < 4; ++q) acc[u][q] = 0.f;

            #pragma unroll
            for (int kc2 = 0; kc2 < 4; ++kc2) {
                uint32_t bh[6][4], bl[6][4];
                #pragma unroll
                for (int u = 0; u < 6; ++u) {
                    uint32_t ab = sb + (uint32_t)((((nb*6 + u)*8 + brow)*WPITCH + 32*kc2 + bko) << 1);
                    LDSM4(bh[u], ab);
                    LDSM4(bl[u], ab + WS_LO);
                }
                #pragma unroll
                for (int u = 0; u < 6; ++u) MMA_BF16(acc[u], ah[2*kc2],   bh[u][0], bh[u][1]);
                #pragma unroll
                for (int u = 0; u < 6; ++u) MMA_BF16(acc[u], ah[2*kc2+1], bh[u][2], bh[u][3]);
                #pragma unroll
                for (int u = 0; u < 6; ++u) MMA_BF16(acc[u], al[2*kc2],   bh[u][0], bh[u][1]);
                #pragma unroll
                for (int u = 0; u < 6; ++u) MMA_BF16(acc[u], al[2*kc2+1], bh[u][2], bh[u][3]);
                #pragma unroll
                for (int u = 0; u < 6; ++u) MMA_BF16(acc[u], ah[2*kc2],   bl[u][0], bl[u][1]);
                #pragma unroll
                for (int u = 0; u < 6; ++u) MMA_BF16(acc[u], ah[2*kc2+1], bl[u][2], bl[u][3]);
            }

            #pragma unroll
            for (int u = 0; u < 6; ++u) {
                const int c0 = (nb*6 + u)*8 + 2*qc;
                float2 bi = *(const float2*)(bsh + c0);
                *(float2*)(g_gi + (size_t)r0*G3 + c0) = make_float2(acc[u][0] + bi.x, acc[u][1] + bi.y);
                *(float2*)(g_gi + (size_t)r1*G3 + c0) = make_float2(acc[u][2] + bi.x, acc[u][3] + bi.y);
            }
        }
    }
}

// ---------------------------------------------------------------------------
// Kernel 2 (NEW): GRU recurrence via mma.sync. 650 CTAs x 16 seqs (exact),
// 8 warps; warp w owns output j in [16w,16w+16) = supertiles {2w,2w+1} in the
// reordered W (colp = (j>>3)*24 + g*8 + (j&7)) = 6 n-tiles = 6 concurrent
// accumulators. h exchanged through smem each step; h_old kept in registers.
// ---------------------------------------------------------------------------
__global__ void __launch_bounds__(256, 1) gru_mma(
    const float* __restrict__ W_hh, const float* __restrict__ b_hh,
    float* __restrict__ out)
{
    extern __shared__ unsigned char smem[];
    __nv_bfloat16* wh = (__nv_bfloat16*)(smem);
    __nv_bfloat16* wl = (__nv_bfloat16*)(smem + WS_LO);
    float* hbuf = (float*)(smem + HB_OFF);           // [16][HP]
    float* bns  = (float*)(smem + BN_OFF);           // b_hh n-gate (128)
    const int tid = threadIdx.x, wid = tid >> 5, lane = tid & 31;

    // Load + split + column-reorder W_hh.
    for (int i = tid; i < G3*DD; i += 256) {
        int n = i >> 7, k = i & 127;
        float w = W_hh[i];
        __nv_bfloat16 hb = __float2bfloat16(w);
        __nv_bfloat16 lb = __float2bfloat16(w - __bfloat162float(hb));
        int g = n >> 7, j = n & 127;
        int colp = (j >> 3)*24 + g*8 + (j & 7);
        wh[colp*WPITCH + k] = hb;
        wl[colp*WPITCH + k] = lb;
    }
    for (int i = tid; i < DD; i += 256) bns[i] = b_hh[2*DD + i];

    const int qr = lane >> 2, qc = lane & 3;
    const int brow = lane & 7, bko = (lane >> 3) << 3;
    const uint32_t sb = smem_u32(smem);
    const int t0 = blockIdx.x * 16;                  // 650*16 = 10400 exact
    const int ta = t0 + qr, tb = ta + 8;             // this thread's two seqs
    const int ja = 16*wid + 2*qc, jb = ja + 8;       // this thread's two j-pairs

    // A fragments (h hi/lo) start at zero (h0 = 0).
    uint32_t ah[8][4], al[8][4];
    #pragma unroll
    for (int kc = 0; kc < 8; ++kc)
        #pragma unroll
        for (int q = 0; q < 4; ++q) { ah[kc][q] = 0u; al[kc][q] = 0u; }
    float h_old[8];
    #pragma unroll
    for (int i = 0; i < 8; ++i) h_old[i] = 0.f;

    __syncthreads();

    for (int l = 0; l < LL; ++l) {
        // gi prefetch for this step (independent of mma; hidden behind it).
        const float* gpa = g_gi + ((size_t)ta*LL + l)*G3;
        const float* gpb = g_gi + ((size_t)tb*LL + l)*G3;
        float2 ira0 = *(const float2*)(gpa + ja);
        float2 iza0 = *(const float2*)(gpa + DD + ja);
        float2 ina0 = *(const float2*)(gpa + 2*DD + ja);
        float2 ira1 = *(const float2*)(gpa + jb);
        float2 iza1 = *(const float2*)(gpa + DD + jb);
        float2 ina1 = *(const float2*)(gpa + 2*DD + jb);
        float2 irb0 = *(const float2*)(gpb + ja);
        float2 izb0 = *(const float2*)(gpb + DD + ja);
        float2 inb0 = *(const float2*)(gpb + 2*DD + ja);
        float2 irb1 = *(const float2*)(gpb + jb);
        float2 izb1 = *(const float2*)(gpb + DD + jb);
        float2 inb1 = *(const float2*)(gpb + 2*DD + jb);

        // ---- mma phase: 6 n-tiles (2 supertiles x 3 gates), 144 mma ----
        float acc[6][4];
        #pragma unroll
        for (int u = 0; u < 6; ++u)
            #pragma unroll
            for (int q = 0; q < 4; ++q) acc[u][q] = 0.f;

        #pragma unroll
        for (int kc2 = 0; kc2 < 4; ++kc2) {
            uint32_t bh[6][4], bl[6][4];
            #pragma unroll
            for (int u = 0; u < 6; ++u) {
                const int st = 2*wid + (u >= 3 ? 1 : 0);
                const int g  = (u >= 3 ? u - 3 : u);
                const int cb = st*24 + g*8;
                uint32_t ab = sb + (uint32_t)(((cb + brow)*WPITCH + 32*kc2 + bko) << 1);
                LDSM4(bh[u], ab);
                LDSM4(bl[u], ab + WS_LO);
            }
            #pragma unroll
            for (int u = 0; u < 6; ++u) MMA_BF16(acc[u], ah[2*kc2],   bh[u][0], bh[u][1]);
            #pragma unroll
            for (int u = 0; u < 6; ++u) MMA_BF16(acc[u], ah[2*kc2+1], bh[u][2], bh[u][3]);
            #pragma unroll
            for (int u = 0; u < 6; ++u) MMA_BF16(acc[u], al[2*kc2],   bh[u][0], bh[u][1]);
            #pragma unroll
            for (int u = 0; u < 6; ++u) MMA_BF16(acc[u], al[2*kc2+1], bh[u][2], bh[u][3]);
            #pragma unroll
            for (int u = 0; u < 6; ++u) MMA_BF16(acc[u], ah[2*kc2],   bl[u][0], bl[u][1]);
            #pragma unroll
            for (int u = 0; u < 6; ++u) MMA_BF16(acc[u], ah[2*kc2+1], bl[u][2], bl[u][3]);
        }

        // ---- epilogue: gates for 2 seqs x 2 j-pairs (8 h values) ----
        float2 bn0 = *(const float2*)(bns + ja);
        float2 bn1 = *(const float2*)(bns + jb);
        float hv[8];
        {   // block 0 (ja): acc[0]=r, acc[1]=z, acc[2]=n
            float r, z, ng;
            r = sigm(ira0.x + acc[0][0]); z = sigm(iza0.x + acc[1][0]);
            ng = tanh_(ina0.x + r*(acc[2][0] + bn0.x));
            hv[0] = (1.f - z)*ng + z*h_old[0];
            r = sigm(ira0.y + acc[0][1]); z = sigm(iza0.y + acc[1][1]);
            ng = tanh_(ina0.y + r*(acc[2][1] + bn0.y));
            hv[1] = (1.f - z)*ng + z*h_old[1];
            r = sigm(irb0.x + acc[0][2]); z = sigm(izb0.x + acc[1][2]);
            ng = tanh_(inb0.x + r*(acc[2][2] + bn0.x));
            hv[2] = (1.f - z)*ng + z*h_old[2];
            r = sigm(irb0.y + acc[0][3]); z = sigm(izb0.y + acc[1][3]);
            ng = tanh_(inb0.y + r*(acc[2][3] + bn0.y));
            hv[3] = (1.f - z)*ng + z*h_old[3];
        }
        {   // block 1 (jb): acc[3]=r, acc[4]=z, acc[5]=n
            float r, z, ng;
            r = sigm(ira1.x + acc[3][0]); z = sigm(iza1.x + acc[4][0]);
            ng = tanh_(ina1.x + r*(acc[5][0] + bn1.x));
            hv[4] = (1.f - z)*ng + z*h_old[4];
            r = sigm(ira1.y + acc[3][1]); z = sigm(iza1.y + acc[4][1]);
            ng = tanh_(ina1.y + r*(acc[5][1] + bn1.y));
            hv[5] = (1.f - z)*ng + z*h_old[5];
            r = sigm(irb1.x + acc[3][2]); z = sigm(izb1.x + acc[4][2]);
            ng = tanh_(inb1.x + r*(acc[5][2] + bn1.x));
            hv[6] = (1.f - z)*ng + z*h_old[6];
            r = sigm(irb1.y + acc[3][3]); z = sigm(izb1.y + acc[4][3]);
            ng = tanh_(inb1.y + r*(acc[5][3] + bn1.y));
            hv[7] = (1.f - z)*ng + z*h_old[7];
        }
        #pragma unroll
        for (int i = 0; i < 8; ++i) h_old[i] = hv[i];

        // Write h to smem (for A rebuild) and out to global.
        *(float2*)(hbuf + qr*HP + ja)      = make_float2(hv[0], hv[1]);
        *(float2*)(hbuf + (qr+8)*HP + ja)  = make_float2(hv[2], hv[3]);
        *(float2*)(hbuf + qr*HP + jb)      = make_float2(hv[4], hv[5]);
        *(float2*)(hbuf + (qr+8)*HP + jb)  = make_float2(hv[6], hv[7]);
        *(float2*)(out + ((size_t)l*BN + ta)*DD + ja) = make_float2(hv[0], hv[1]);
        *(float2*)(out + ((size_t)l*BN + tb)*DD + ja) = make_float2(hv[2], hv[3]);
        *(float2*)(out + ((size_t)l*BN + ta)*DD + jb) = make_float2(hv[4], hv[5]);
        *(float2*)(out + ((size_t)l*BN + tb)*DD + jb) = make_float2(hv[6], hv[7]);
        __syncthreads();

        // Rebuild A fragments (hi/lo split) from the full h[16][128] in smem.
        if (l + 1 < LL) {
            #pragma unroll
            for (int kc = 0; kc < 8; ++kc) {
                float2 xa = *(const float2*)(hbuf + qr*HP     + 16*kc + 2*qc);
                float2 xb = *(const float2*)(hbuf + (qr+8)*HP + 16*kc + 2*qc);
                float2 xc = *(const float2*)(hbuf + qr*HP     + 16*kc + 8 + 2*qc);
                float2 xd = *(const float2*)(hbuf + (qr+8)*HP + 16*kc + 8 + 2*qc);
                uint32_t H;
                H = pbf2(xa.x, xa.y); ah[kc][0] = H; { float2 c = ubf2(H); al[kc][0] = pbf2(xa.x - c.x, xa.y - c.y); }
                H = pbf2(xb.x, xb.y); ah[kc][1] = H; { float2 c = ubf2(H); al[kc][1] = pbf2(xb.x - c.x, xb.y - c.y); }
                H = pbf2(xc.x, xc.y); ah[kc][2] = H; { float2 c = ubf2(H); al[kc][2] = pbf2(xc.x - c.x, xc.y - c.y); }
                H = pbf2(xd.x, xd.y); ah[kc][3] = H; { float2 c = ubf2(H); al[kc][3] = pbf2(xd.x - c.x, xd.y - c.y); }
            }
            __syncthreads();   // rebuild reads done before next step's h writes
        }
    }
}

extern "C" void kernel_launch(void* const* d_in, const int* in_sizes, int n_in,
                              void* d_out, int out_size)
{
    const float* X    = (const float*)d_in[0];
    const float* W_ih = (const float*)d_in[1];
    const float* W_hh = (const float*)d_in[2];
    const float* b_ih = (const float*)d_in[3];
    const float* b_hh = (const float*)d_in[4];
    float* out = (float*)d_out;

    cudaFuncSetAttribute(gi_mma,  cudaFuncAttributeMaxDynamicSharedMemorySize, SMEM_GIMMA);
    cudaFuncSetAttribute(gru_mma, cudaFuncAttributeMaxDynamicSharedMemorySize, SMEM_GRUMMA);

    gi_mma<<<148, 256, SMEM_GIMMA>>>(X, W_ih, b_ih, b_hh);
    gru_mma<<<BN/16, 256, SMEM_GRUMMA>>>(W_hh, b_hh, out);   // 650 CTAs x 16 seqs
}

// round 16
// speedup vs baseline: 2.9423x; 1.0445x over previous
#include <cuda_runtime.h>
#include <cuda_fp16.h>
#include <cstdint>

#define BB 32
#define LL 48
#define NN 325
#define DD 128
#define G3 384
#define BN (BB*NN)             // 10400 sequences
#define ROWS (BN*LL)           // 499200 gi rows

typedef unsigned long long ull;

// Scratch for input-side gate projections: gi[t][l][g], row r = t*LL+l.
// Folded bias: b_ih + b_hh for gates r,z; b_ih only for gate n.
__device__ float g_gi[(size_t)ROWS * G3];

// ===================== helpers =============================================
__device__ __forceinline__ float sigm(float x)  { return 1.f / (1.f + __expf(-x)); }
__device__ __forceinline__ float tanh_(float x) { return 1.f - 2.f / (__expf(2.f*x) + 1.f); }

__device__ __forceinline__ uint32_t smem_u32(const void* p) {
    uint32_t a;
    asm("{ .reg .u64 t; cvta.to.shared.u64 t, %1; cvt.u32.u64 %0, t; }" : "=r"(a) : "l"(p));
    return a;
}
#define MMA_F16(c, a, b0_, b1_) \
    asm volatile("mma.sync.aligned.m16n8k16.row.col.f32.f16.f16.f32 " \
        "{%0,%1,%2,%3}, {%4,%5,%6,%7}, {%8,%9}, {%0,%1,%2,%3};" \
        : "+f"((c)[0]), "+f"((c)[1]), "+f"((c)[2]), "+f"((c)[3]) \
        : "r"((a)[0]), "r"((a)[1]), "r"((a)[2]), "r"((a)[3]), "r"(b0_), "r"(b1_))

#define LDSM4(r, addr) \
    asm volatile("ldmatrix.sync.aligned.m8n8.x4.shared.b16 {%0,%1,%2,%3}, [%4];" \
        : "=r"((r)[0]), "=r"((r)[1]), "=r"((r)[2]), "=r"((r)[3]) : "r"(addr))

__device__ __forceinline__ uint32_t pH2(float x, float y) {
    __half2 t = __floats2half2_rn(x, y);
    return *(uint32_t*)&t;
}

// W tiles in shared: pitch 136 f16 (=272B = 17x16B -> ldmatrix row pointers
// hit distinct 16B banks).
#define WPITCH 136
#define WS_LO  (G3*WPITCH*2)          // 104448

// gi_mma layout
#define BI_OFF (2*G3*WPITCH*2)        // 208896
#define SMEM_GIMMA (BI_OFF + 1536 + 64)

// gru_mma layout (double-buffered h)
#define HP 130
#define HB_OFF (2*G3*WPITCH*2)        // 208896
#define HBUF_BYTES (2*16*HP*4)        // 16640
#define BN_OFF (HB_OFF + HBUF_BYTES)  // 225536
#define SMEM_GRUMMA (BN_OFF + 512 + 64)   // 226112 < 227KB cap

// ---------------------------------------------------------------------------
// Kernel 1: gi via mma.sync f16 2-term (A = x_f16; W = Whi + Wlo, both f16).
// 148 CTAs x 8 warps; bias fold: r,z get b_ih+b_hh; n gets b_ih.
// ---------------------------------------------------------------------------
__global__ void __launch_bounds__(256, 1) gi_mma(
    const float* __restrict__ X, const float* __restrict__ W_ih,
    const float* __restrict__ b_ih, const float* __restrict__ b_hh)
{
    extern __shared__ unsigned char smem[];
    __half* wh = (__half*)(smem);
    __half* wl = (__half*)(smem + WS_LO);
    float* bsh = (float*)(smem + BI_OFF);
    const int tid = threadIdx.x, wid = tid >> 5, lane = tid & 31;

    for (int i = tid; i < G3*DD; i += 256) {
        int col = i >> 7, k = i & 127;
        float w = W_ih[i];
        __half hb = __float2half_rn(w);
        __half lb = __float2half_rn(w - __half2float(hb));
        wh[col*WPITCH + k] = hb;
        wl[col*WPITCH + k] = lb;
    }
    for (int i = tid; i < G3; i += 256)
        bsh[i] = b_ih[i] + (i < 2*DD ? b_hh[i] : 0.f);
    __syncthreads();

    const int qr = lane >> 2, qc = lane & 3;
    const int brow = lane & 7, bko = (lane >> 3) << 3;
    const uint32_t sb = smem_u32(smem);

    const int NT = ROWS / 16;              // 31200 row-tiles
    const int wg = blockIdx.x*8 + wid;
    for (int rt = wg; rt < NT; rt += 148*8) {
        const int r0 = rt*16 + qr;
        const int r1 = r0 + 8;
        int t0 = r0 / LL, l0 = r0 - t0*LL;
        int t1 = r1 / LL, l1 = r1 - t1*LL;
        int b0i = t0 / NN, n0 = t0 - b0i*NN;
        int b1i = t1 / NN, n1 = t1 - b1i*NN;
        const float* px0 = X + ((size_t)(b0i*LL + l0)*NN + n0)*DD;
        const float* px1 = X + ((size_t)(b1i*LL + l1)*NN + n1)*DD;

        // A fragments: x in plain f16 ({kLo(r0), kLo(r1), kHi(r0), kHi(r1)}).
        uint32_t ah[8][4];
        #pragma unroll
        for (int kc = 0; kc < 8; ++kc) {
            float2 xa = *(const float2*)(px0 + 16*kc + 2*qc);
            float2 xb = *(const float2*)(px1 + 16*kc + 2*qc);
            float2 xc = *(const float2*)(px0 + 16*kc + 8 + 2*qc);
            float2 xd = *(const float2*)(px1 + 16*kc + 8 + 2*qc);
            ah[kc][0] = pH2(xa.x, xa.y);
            ah[kc][1] = pH2(xb.x, xb.y);
            ah[kc][2] = pH2(xc.x, xc.y);
            ah[kc][3] = pH2(xd.x, xd.y);
        }

        #pragma unroll 1
        for (int nb = 0; nb < 8; ++nb) {
            float acc[6][4];
            #pragma unroll
            for (int u = 0; u < 6; ++u)
                #pragma unroll
                for (int q = 0; q < 4; ++q) acc[u][q] = 0.f;

            #pragma unroll
            for (int kc2 = 0; kc2 < 4; ++kc2) {
                uint32_t bh[6][4], bl[6][4];
                #pragma unroll
                for (int u = 0; u < 6; ++u) {
                    uint32_t ab = sb + (uint32_t)((((nb*6 + u)*8 + brow)*WPITCH + 32*kc2 + bko) << 1);
                    LDSM4(bh[u], ab);
                    LDSM4(bl[u], ab + WS_LO);
                }
                #pragma unroll
                for (int u = 0; u < 6; ++u) MMA_F16(acc[u], ah[2*kc2],   bh[u][0], bh[u][1]);
                #pragma unroll
                for (int u = 0; u < 6; ++u) MMA_F16(acc[u], ah[2*kc2+1], bh[u][2], bh[u][3]);
                #pragma unroll
                for (int u = 0; u < 6; ++u) MMA_F16(acc[u], ah[2*kc2],   bl[u][0], bl[u][1]);
                #pragma unroll
                for (int u = 0; u < 6; ++u) MMA_F16(acc[u], ah[2*kc2+1], bl[u][2], bl[u][3]);
            }

            #pragma unroll
            for (int u = 0; u < 6; ++u) {
                const int c0 = (nb*6 + u)*8 + 2*qc;
                float2 bi = *(const float2*)(bsh + c0);
                *(float2*)(g_gi + (size_t)r0*G3 + c0) = make_float2(acc[u][0] + bi.x, acc[u][1] + bi.y);
                *(float2*)(g_gi + (size_t)r1*G3 + c0) = make_float2(acc[u][2] + bi.x, acc[u][3] + bi.y);
            }
        }
    }
}

// ---------------------------------------------------------------------------
// Kernel 2: GRU recurrence via mma.sync f16 2-term. 650 CTAs x 16 seqs,
// 8 warps; warp w owns j in [16w,16w+16) (6 n-tiles / 6 accumulators).
// h double-buffered in smem -> ONE barrier per step. B frags double-buffered
// across kc2. h_old in registers.
// ---------------------------------------------------------------------------
__device__ __forceinline__ void loadB(
    uint32_t sb, int wid, int brow, int bko, int kc2,
    uint32_t bh[6][4], uint32_t bl[6][4])
{
    #pragma unroll
    for (int u = 0; u < 6; ++u) {
        const int st = 2*wid + (u >= 3 ? 1 : 0);
        const int g  = (u >= 3 ? u - 3 : u);
        uint32_t ab = sb + (uint32_t)((((st*24 + g*8) + brow)*WPITCH + 32*kc2 + bko) << 1);
        LDSM4(bh[u], ab);
        LDSM4(bl[u], ab + WS_LO);
    }
}

__global__ void __launch_bounds__(256, 1) gru_mma(
    const float* __restrict__ W_hh, const float* __restrict__ b_hh,
    float* __restrict__ out)
{
    extern __shared__ unsigned char smem[];
    __half* wh = (__half*)(smem);
    __half* wl = (__half*)(smem + WS_LO);
    float* hbuf = (float*)(smem + HB_OFF);           // [2][16][HP]
    float* bns  = (float*)(smem + BN_OFF);           // b_hh n-gate
    const int tid = threadIdx.x, wid = tid >> 5, lane = tid & 31;

    // Load + f16-split + column-reorder W_hh: colp = (j>>3)*24 + g*8 + (j&7).
    for (int i = tid; i < G3*DD; i += 256) {
        int n = i >> 7, k = i & 127;
        float w = W_hh[i];
        __half hb = __float2half_rn(w);
        __half lb = __float2half_rn(w - __half2float(hb));
        int g = n >> 7, j = n & 127;
        int colp = (j >> 3)*24 + g*8 + (j & 7);
        wh[colp*WPITCH + k] = hb;
        wl[colp*WPITCH + k] = lb;
    }
    for (int i = tid; i < DD; i += 256) bns[i] = b_hh[2*DD + i];

    const int qr = lane >> 2, qc = lane & 3;
    const int brow = lane & 7, bko = (lane >> 3) << 3;
    const uint32_t sb = smem_u32(smem);
    const int t0 = blockIdx.x * 16;                  // 650*16 = 10400 exact
    const int ta = t0 + qr, tb = ta + 8;
    const int ja = 16*wid + 2*qc, jb = ja + 8;

    // A fragments (h as f16) start at zero.
    uint32_t ah[8][4];
    #pragma unroll
    for (int kc = 0; kc < 8; ++kc)
        #pragma unroll
        for (int q = 0; q < 4; ++q) ah[kc][q] = 0u;
    float h_old[8];
    #pragma unroll
    for (int i = 0; i < 8; ++i) h_old[i] = 0.f;

    __syncthreads();

    for (int l = 0; l < LL; ++l) {
        // gi prefetch for this step (hidden behind mma phase).
        const float* gpa = g_gi + ((size_t)ta*LL + l)*G3;
        const float* gpb = g_gi + ((size_t)tb*LL + l)*G3;
        float2 ira0 = *(const float2*)(gpa + ja);
        float2 iza0 = *(const float2*)(gpa + DD + ja);
        float2 ina0 = *(const float2*)(gpa + 2*DD + ja);
        float2 ira1 = *(const float2*)(gpa + jb);
        float2 iza1 = *(const float2*)(gpa + DD + jb);
        float2 ina1 = *(const float2*)(gpa + 2*DD + jb);
        float2 irb0 = *(const float2*)(gpb + ja);
        float2 izb0 = *(const float2*)(gpb + DD + ja);
        float2 inb0 = *(const float2*)(gpb + 2*DD + ja);
        float2 irb1 = *(const float2*)(gpb + jb);
        float2 izb1 = *(const float2*)(gpb + DD + jb);
        float2 inb1 = *(const float2*)(gpb + 2*DD + jb);

        // ---- mma phase: 96 mma, B double-buffered across kc2 ----
        float acc[6][4];
        #pragma unroll
        for (int u = 0; u < 6; ++u)
            #pragma unroll
            for (int q = 0; q < 4; ++q) acc[u][q] = 0.f;

        uint32_t bh[2][6][4], bl[2][6][4];
        loadB(sb, wid, brow, bko, 0, bh[0], bl[0]);
        #pragma unroll
        for (int kc2 = 0; kc2 < 4; ++kc2) {
            const int cur = kc2 & 1, nxt = cur ^ 1;
            if (kc2 < 3) loadB(sb, wid, brow, bko, kc2 + 1, bh[nxt], bl[nxt]);
            #pragma unroll
            for (int u = 0; u < 6; ++u) MMA_F16(acc[u], ah[2*kc2],   bh[cur][u][0], bh[cur][u][1]);
            #pragma unroll
            for (int u = 0; u < 6; ++u) MMA_F16(acc[u], ah[2*kc2+1], bh[cur][u][2], bh[cur][u][3]);
            #pragma unroll
            for (int u = 0; u < 6; ++u) MMA_F16(acc[u], ah[2*kc2],   bl[cur][u][0], bl[cur][u][1]);
            #pragma unroll
            for (int u = 0; u < 6; ++u) MMA_F16(acc[u], ah[2*kc2+1], bl[cur][u][2], bl[cur][u][3]);
        }

        // ---- epilogue: gates for 8 h values ----
        float2 bn0 = *(const float2*)(bns + ja);
        float2 bn1 = *(const float2*)(bns + jb);
        float hv[8];
        {
            float r, z, ng;
            r = sigm(ira0.x + acc[0][0]); z = sigm(iza0.x + acc[1][0]);
            ng = tanh_(ina0.x + r*(acc[2][0] + bn0.x));
            hv[0] = (1.f - z)*ng + z*h_old[0];
            r = sigm(ira0.y + acc[0][1]); z = sigm(iza0.y + acc[1][1]);
            ng = tanh_(ina0.y + r*(acc[2][1] + bn0.y));
            hv[1] = (1.f - z)*ng + z*h_old[1];
            r = sigm(irb0.x + acc[0][2]); z = sigm(izb0.x + acc[1][2]);
            ng = tanh_(inb0.x + r*(acc[2][2] + bn0.x));
            hv[2] = (1.f - z)*ng + z*h_old[2];
            r = sigm(irb0.y + acc[0][3]); z = sigm(izb0.y + acc[1][3]);
            ng = tanh_(inb0.y + r*(acc[2][3] + bn0.y));
            hv[3] = (1.f - z)*ng + z*h_old[3];
        }
        {
            float r, z, ng;
            r = sigm(ira1.x + acc[3][0]); z = sigm(iza1.x + acc[4][0]);
            ng = tanh_(ina1.x + r*(acc[5][0] + bn1.x));
            hv[4] = (1.f - z)*ng + z*h_old[4];
            r = sigm(ira1.y + acc[3][1]); z = sigm(iza1.y + acc[4][1]);
            ng = tanh_(ina1.y + r*(acc[5][1] + bn1.y));
            hv[5] = (1.f - z)*ng + z*h_old[5];
            r = sigm(irb1.x + acc[3][2]); z = sigm(izb1.x + acc[4][2]);
            ng = tanh_(inb1.x + r*(acc[5][2] + bn1.x));
            hv[6] = (1.f - z)*ng + z*h_old[6];
            r = sigm(irb1.y + acc[3][3]); z = sigm(izb1.y + acc[4][3]);
            ng = tanh_(inb1.y + r*(acc[5][3] + bn1.y));
            hv[7] = (1.f - z)*ng + z*h_old[7];
        }
        #pragma unroll
        for (int i = 0; i < 8; ++i) h_old[i] = hv[i];

        // Write h to this step's buffer + out to global; ONE barrier.
        float* hb = hbuf + (l & 1) * (16*HP);
        *(float2*)(hb + qr*HP + ja)      = make_float2(hv[0], hv[1]);
        *(float2*)(hb + (qr+8)*HP + ja)  = make_float2(hv[2], hv[3]);
        *(float2*)(hb + qr*HP + jb)      = make_float2(hv[4], hv[5]);
        *(float2*)(hb + (qr+8)*HP + jb)  = make_float2(hv[6], hv[7]);
        *(float2*)(out + ((size_t)l*BN + ta)*DD + ja) = make_float2(hv[0], hv[1]);
        *(float2*)(out + ((size_t)l*BN + tb)*DD + ja) = make_float2(hv[2], hv[3]);
        *(float2*)(out + ((size_t)l*BN + ta)*DD + jb) = make_float2(hv[4], hv[5]);
        *(float2*)(out + ((size_t)l*BN + tb)*DD + jb) = make_float2(hv[6], hv[7]);
        __syncthreads();

        // Rebuild A (f16) from this step's buffer. Next step writes the other
        // buffer, so no second barrier is needed.
        if (l + 1 < LL) {
            #pragma unroll
            for (int kc = 0; kc < 8; ++kc) {
                float2 xa = *(const float2*)(hb + qr*HP     + 16*kc + 2*qc);
                float2 xb = *(const float2*)(hb + (qr+8)*HP + 16*kc + 2*qc);
                float2 xc = *(const float2*)(hb + qr*HP     + 16*kc + 8 + 2*qc);
                float2 xd = *(const float2*)(hb + (qr+8)*HP + 16*kc + 8 + 2*qc);
                ah[kc][0] = pH2(xa.x, xa.y);
                ah[kc][1] = pH2(xb.x, xb.y);
                ah[kc][2] = pH2(xc.x, xc.y);
                ah[kc][3] = pH2(xd.x, xd.y);
            }
        }
    }
}

extern "C" void kernel_launch(void* const* d_in, const int* in_sizes, int n_in,
                              void* d_out, int out_size)
{
    const float* X    = (const float*)d_in[0];
    const float* W_ih = (const float*)d_in[1];
    const float* W_hh = (const float*)d_in[2];
    const float* b_ih = (const float*)d_in[3];
    const float* b_hh = (const float*)d_in[4];
    float* out = (float*)d_out;

    cudaFuncSetAttribute(gi_mma,  cudaFuncAttributeMaxDynamicSharedMemorySize, SMEM_GIMMA);
    cudaFuncSetAttribute(gru_mma, cudaFuncAttributeMaxDynamicSharedMemorySize, SMEM_GRUMMA);

    gi_mma<<<148, 256, SMEM_GIMMA>>>(X, W_ih, b_ih, b_hh);
    gru_mma<<<BN/16, 256, SMEM_GRUMMA>>>(W_hh, b_hh, out);   // 650 CTAs x 16 seqs
}

// round 17
// speedup vs baseline: 3.8273x; 1.3008x over previous
#include <cuda_runtime.h>
#include <cuda_fp16.h>
#include <cstdint>

#define BB 32
#define LL 48
#define NN 325
#define DD 128
#define G3 384
#define BN (BB*NN)             // 10400 sequences
#define ROWS (BN*LL)           // 499200 gi rows

typedef unsigned long long ull;

// Scratch for input-side gate projections: gi[t][l][g], row r = t*LL+l.
// Folded bias: b_ih + b_hh for gates r,z; b_ih only for gate n.
__device__ float g_gi[(size_t)ROWS * G3];

// ===================== helpers =============================================
__device__ __forceinline__ float sigm(float x)  { return 1.f / (1.f + __expf(-x)); }
__device__ __forceinline__ float tanh_(float x) { return 1.f - 2.f / (__expf(2.f*x) + 1.f); }

__device__ __forceinline__ uint32_t smem_u32(const void* p) {
    uint32_t a;
    asm("{ .reg .u64 t; cvta.to.shared.u64 t, %1; cvt.u32.u64 %0, t; }" : "=r"(a) : "l"(p));
    return a;
}
#define MMA_F16(c, a, b0_, b1_) \
    asm volatile("mma.sync.aligned.m16n8k16.row.col.f32.f16.f16.f32 " \
        "{%0,%1,%2,%3}, {%4,%5,%6,%7}, {%8,%9}, {%0,%1,%2,%3};" \
        : "+f"((c)[0]), "+f"((c)[1]), "+f"((c)[2]), "+f"((c)[3]) \
        : "r"((a)[0]), "r"((a)[1]), "r"((a)[2]), "r"((a)[3]), "r"(b0_), "r"(b1_))

#define LDSM4(r, addr) \
    asm volatile("ldmatrix.sync.aligned.m8n8.x4.shared.b16 {%0,%1,%2,%3}, [%4];" \
        : "=r"((r)[0]), "=r"((r)[1]), "=r"((r)[2]), "=r"((r)[3]) : "r"(addr))

__device__ __forceinline__ uint32_t pH2(float x, float y) {
    __half2 t = __floats2half2_rn(x, y);
    return *(uint32_t*)&t;
}

// W tiles in shared: pitch 136 f16 (=272B = 17x16B -> ldmatrix row pointers
// hit distinct 16B banks).
#define WPITCH 136
#define WS_LO  (G3*WPITCH*2)          // 104448

// gi_mma layout
#define BI_OFF (2*G3*WPITCH*2)        // 208896
#define SMEM_GIMMA (BI_OFF + 1536 + 64)

// gru_mma layout: h exchange buffers in f16, pitch 136 halfs (272B rows).
// Per group: 2 step-parity buffers x 16 rows. Two groups.
#define HPH 136
#define HBH_OFF (2*G3*WPITCH*2)       // 208896
#define HBUF_GRP (2*16*HPH*2)         // 8704 bytes per group
#define BN_OFF (HBH_OFF + 2*HBUF_GRP) // 226304
#define SMEM_GRUMMA (BN_OFF + 512 + 64)   // 226880 < 232448 cap

// ---------------------------------------------------------------------------
// Kernel 1 (proven R15): gi via mma.sync f16 2-term. 148 CTAs x 8 warps.
// ---------------------------------------------------------------------------
__global__ void __launch_bounds__(256, 1) gi_mma(
    const float* __restrict__ X, const float* __restrict__ W_ih,
    const float* __restrict__ b_ih, const float* __restrict__ b_hh)
{
    extern __shared__ unsigned char smem[];
    __half* wh = (__half*)(smem);
    __half* wl = (__half*)(smem + WS_LO);
    float* bsh = (float*)(smem + BI_OFF);
    const int tid = threadIdx.x, wid = tid >> 5, lane = tid & 31;

    for (int i = tid; i < G3*DD; i += 256) {
        int col = i >> 7, k = i & 127;
        float w = W_ih[i];
        __half hb = __float2half_rn(w);
        __half lb = __float2half_rn(w - __half2float(hb));
        wh[col*WPITCH + k] = hb;
        wl[col*WPITCH + k] = lb;
    }
    for (int i = tid; i < G3; i += 256)
        bsh[i] = b_ih[i] + (i < 2*DD ? b_hh[i] : 0.f);
    __syncthreads();

    const int qr = lane >> 2, qc = lane & 3;
    const int brow = lane & 7, bko = (lane >> 3) << 3;
    const uint32_t sb = smem_u32(smem);

    const int NT = ROWS / 16;              // 31200 row-tiles
    const int wg = blockIdx.x*8 + wid;
    for (int rt = wg; rt < NT; rt += 148*8) {
        const int r0 = rt*16 + qr;
        const int r1 = r0 + 8;
        int t0 = r0 / LL, l0 = r0 - t0*LL;
        int t1 = r1 / LL, l1 = r1 - t1*LL;
        int b0i = t0 / NN, n0 = t0 - b0i*NN;
        int b1i = t1 / NN, n1 = t1 - b1i*NN;
        const float* px0 = X + ((size_t)(b0i*LL + l0)*NN + n0)*DD;
        const float* px1 = X + ((size_t)(b1i*LL + l1)*NN + n1)*DD;

        uint32_t ah[8][4];
        #pragma unroll
        for (int kc = 0; kc < 8; ++kc) {
            float2 xa = *(const float2*)(px0 + 16*kc + 2*qc);
            float2 xb = *(const float2*)(px1 + 16*kc + 2*qc);
            float2 xc = *(const float2*)(px0 + 16*kc + 8 + 2*qc);
            float2 xd = *(const float2*)(px1 + 16*kc + 8 + 2*qc);
            ah[kc][0] = pH2(xa.x, xa.y);
            ah[kc][1] = pH2(xb.x, xb.y);
            ah[kc][2] = pH2(xc.x, xc.y);
            ah[kc][3] = pH2(xd.x, xd.y);
        }

        #pragma unroll 1
        for (int nb = 0; nb < 8; ++nb) {
            float acc[6][4];
            #pragma unroll
            for (int u = 0; u < 6; ++u)
                #pragma unroll
                for (int q = 0; q < 4; ++q) acc[u][q] = 0.f;

            #pragma unroll
            for (int kc2 = 0; kc2 < 4; ++kc2) {
                uint32_t bh[6][4], bl[6][4];
                #pragma unroll
                for (int u = 0; u < 6; ++u) {
                    uint32_t ab = sb + (uint32_t)((((nb*6 + u)*8 + brow)*WPITCH + 32*kc2 + bko) << 1);
                    LDSM4(bh[u], ab);
                    LDSM4(bl[u], ab + WS_LO);
                }
                #pragma unroll
                for (int u = 0; u < 6; ++u) MMA_F16(acc[u], ah[2*kc2],   bh[u][0], bh[u][1]);
                #pragma unroll
                for (int u = 0; u < 6; ++u) MMA_F16(acc[u], ah[2*kc2+1], bh[u][2], bh[u][3]);
                #pragma unroll
                for (int u = 0; u < 6; ++u) MMA_F16(acc[u], ah[2*kc2],   bl[u][0], bl[u][1]);
                #pragma unroll
                for (int u = 0; u < 6; ++u) MMA_F16(acc[u], ah[2*kc2+1], bl[u][2], bl[u][3]);
            }

            #pragma unroll
            for (int u = 0; u < 6; ++u) {
                const int c0 = (nb*6 + u)*8 + 2*qc;
                float2 bi = *(const float2*)(bsh + c0);
                *(float2*)(g_gi + (size_t)r0*G3 + c0) = make_float2(acc[u][0] + bi.x, acc[u][1] + bi.y);
                *(float2*)(g_gi + (size_t)r1*G3 + c0) = make_float2(acc[u][2] + bi.x, acc[u][3] + bi.y);
            }
        }
    }
}

// ---------------------------------------------------------------------------
// Kernel 2: GRU recurrence via mma.sync f16 2-term. 325 CTAs x 512 threads:
// TWO independent 16-seq groups per CTA (warps 0-7 / 8-15) sharing W tiles.
// Named barriers per group. 4 warps/SMSP -> two chains hide each other's
// latency; 2.2 waves instead of 4.4. h exchange buffer in f16 (rebuild =
// raw LDS.32, no converts). One supertile (3 accs) in flight at a time to
// fit the 128-reg/thread budget.
// ---------------------------------------------------------------------------
__global__ void __launch_bounds__(512, 1) gru_mma(
    const float* __restrict__ W_hh, const float* __restrict__ b_hh,
    float* __restrict__ out)
{
    extern __shared__ unsigned char smem[];
    __half* wh = (__half*)(smem);
    __half* wl = (__half*)(smem + WS_LO);
    float* bns = (float*)(smem + BN_OFF);            // b_hh n-gate
    const int tid = threadIdx.x, wid = tid >> 5, lane = tid & 31;
    const int gid = wid >> 3;                        // seq-group 0/1
    const int wg  = wid & 7;                         // warp within group

    // Load + f16-split + column-reorder W_hh: colp = (j>>3)*24 + g*8 + (j&7).
    for (int i = tid; i < G3*DD; i += 512) {
        int n = i >> 7, k = i & 127;
        float w = W_hh[i];
        __half hb = __float2half_rn(w);
        __half lb = __float2half_rn(w - __half2float(hb));
        int g = n >> 7, j = n & 127;
        int colp = (j >> 3)*24 + g*8 + (j & 7);
        wh[colp*WPITCH + k] = hb;
        wl[colp*WPITCH + k] = lb;
    }
    for (int i = tid; i < DD; i += 512) bns[i] = b_hh[2*DD + i];

    const int qr = lane >> 2, qc = lane & 3;
    const int brow = lane & 7, bko = (lane >> 3) << 3;
    const uint32_t sb = smem_u32(smem);
    __half* hgrp = (__half*)(smem + HBH_OFF) + gid * (2*16*HPH);

    const int t0 = blockIdx.x*32 + gid*16;           // 325*32 = 10400 exact
    const int ta = t0 + qr, tb = ta + 8;
    const int ja = 16*wg + 2*qc, jb = ja + 8;

    uint32_t ah[8][4];
    #pragma unroll
    for (int kc = 0; kc < 8; ++kc)
        #pragma unroll
        for (int q = 0; q < 4; ++q) ah[kc][q] = 0u;
    float h_old[8];
    #pragma unroll
    for (int i = 0; i < 8; ++i) h_old[i] = 0.f;

    __syncthreads();

    for (int l = 0; l < LL; ++l) {
        // gi prefetch for this step (hidden behind the mma passes).
        const float* gpa = g_gi + ((size_t)ta*LL + l)*G3;
        const float* gpb = g_gi + ((size_t)tb*LL + l)*G3;
        float2 ira0 = *(const float2*)(gpa + ja);
        float2 iza0 = *(const float2*)(gpa + DD + ja);
        float2 ina0 = *(const float2*)(gpa + 2*DD + ja);
        float2 irb0 = *(const float2*)(gpb + ja);
        float2 izb0 = *(const float2*)(gpb + DD + ja);
        float2 inb0 = *(const float2*)(gpb + 2*DD + ja);
        float2 ira1 = *(const float2*)(gpa + jb);
        float2 iza1 = *(const float2*)(gpa + DD + jb);
        float2 ina1 = *(const float2*)(gpa + 2*DD + jb);
        float2 irb1 = *(const float2*)(gpb + jb);
        float2 izb1 = *(const float2*)(gpb + DD + jb);
        float2 inb1 = *(const float2*)(gpb + 2*DD + jb);

        float hv[8];
        float2 bn0 = *(const float2*)(bns + ja);
        float2 bn1 = *(const float2*)(bns + jb);

        // ---- two supertile passes (3 gates / 3 accumulators each) ----
        #pragma unroll
        for (int st = 0; st < 2; ++st) {
            float acc[3][4];
            #pragma unroll
            for (int g = 0; g < 3; ++g)
                #pragma unroll
                for (int q = 0; q < 4; ++q) acc[g][q] = 0.f;

            const int cb = (2*wg + st)*24;
            #pragma unroll
            for (int kc2 = 0; kc2 < 4; ++kc2) {
                uint32_t bh[3][4], bl[3][4];
                #pragma unroll
                for (int g = 0; g < 3; ++g) {
                    uint32_t ab = sb + (uint32_t)(((cb + g*8 + brow)*WPITCH + 32*kc2 + bko) << 1);
                    LDSM4(bh[g], ab);
                    LDSM4(bl[g], ab + WS_LO);
                }
                #pragma unroll
                for (int g = 0; g < 3; ++g) MMA_F16(acc[g], ah[2*kc2],   bh[g][0], bh[g][1]);
                #pragma unroll
                for (int g = 0; g < 3; ++g) MMA_F16(acc[g], ah[2*kc2+1], bh[g][2], bh[g][3]);
                #pragma unroll
                for (int g = 0; g < 3; ++g) MMA_F16(acc[g], ah[2*kc2],   bl[g][0], bl[g][1]);
                #pragma unroll
                for (int g = 0; g < 3; ++g) MMA_F16(acc[g], ah[2*kc2+1], bl[g][2], bl[g][3]);
            }

            // ---- per-pass epilogue: 4 h values ----
            float2 ir_a = st ? ira1 : ira0, iz_a = st ? iza1 : iza0, in_a = st ? ina1 : ina0;
            float2 ir_b = st ? irb1 : irb0, iz_b = st ? izb1 : izb0, in_b = st ? inb1 : inb0;
            float2 bnv  = st ? bn1 : bn0;
            float r, z, ng;
            r = sigm(ir_a.x + acc[0][0]); z = sigm(iz_a.x + acc[1][0]);
            ng = tanh_(in_a.x + r*(acc[2][0] + bnv.x));
            hv[4*st+0] = (1.f - z)*ng + z*h_old[4*st+0];
            r = sigm(ir_a.y + acc[0][1]); z = sigm(iz_a.y + acc[1][1]);
            ng = tanh_(in_a.y + r*(acc[2][1] + bnv.y));
            hv[4*st+1] = (1.f - z)*ng + z*h_old[4*st+1];
            r = sigm(ir_b.x + acc[0][2]); z = sigm(iz_b.x + acc[1][2]);
            ng = tanh_(in_b.x + r*(acc[2][2] + bnv.x));
            hv[4*st+2] = (1.f - z)*ng + z*h_old[4*st+2];
            r = sigm(ir_b.y + acc[0][3]); z = sigm(iz_b.y + acc[1][3]);
            ng = tanh_(in_b.y + r*(acc[2][3] + bnv.y));
            hv[4*st+3] = (1.f - z)*ng + z*h_old[4*st+3];
        }
        #pragma unroll
        for (int i = 0; i < 8; ++i) h_old[i] = hv[i];

        // Write h (f16) to this step's buffer + f32 out; named group barrier.
        __half* hb = hgrp + (l & 1) * (16*HPH);
        *(uint32_t*)(hb + qr*HPH + ja)     = pH2(hv[0], hv[1]);
        *(uint32_t*)(hb + (qr+8)*HPH + ja) = pH2(hv[2], hv[3]);
        *(uint32_t*)(hb + qr*HPH + jb)     = pH2(hv[4], hv[5]);
        *(uint32_t*)(hb + (qr+8)*HPH + jb) = pH2(hv[6], hv[7]);
        *(float2*)(out + ((size_t)l*BN + ta)*DD + ja) = make_float2(hv[0], hv[1]);
        *(float2*)(out + ((size_t)l*BN + tb)*DD + ja) = make_float2(hv[2], hv[3]);
        *(float2*)(out + ((size_t)l*BN + ta)*DD + jb) = make_float2(hv[4], hv[5]);
        *(float2*)(out + ((size_t)l*BN + tb)*DD + jb) = make_float2(hv[6], hv[7]);
        asm volatile("bar.sync %0, %1;" :: "r"(gid + 1), "r"(256) : "memory");

        // Rebuild A (raw 4B LDS of half2 pairs, zero converts). Next step
        // writes the other parity buffer -> no second barrier needed.
        if (l + 1 < LL) {
            #pragma unroll
            for (int kc = 0; kc < 8; ++kc) {
                ah[kc][0] = *(const uint32_t*)(hb + qr*HPH     + 16*kc + 2*qc);
                ah[kc][1] = *(const uint32_t*)(hb + (qr+8)*HPH + 16*kc + 2*qc);
                ah[kc][2] = *(const uint32_t*)(hb + qr*HPH     + 16*kc + 8 + 2*qc);
                ah[kc][3] = *(const uint32_t*)(hb + (qr+8)*HPH + 16*kc + 8 + 2*qc);
            }
        }
    }
}

extern "C" void kernel_launch(void* const* d_in, const int* in_sizes, int n_in,
                              void* d_out, int out_size)
{
    const float* X    = (const float*)d_in[0];
    const float* W_ih = (const float*)d_in[1];
    const float* W_hh = (const float*)d_in[2];
    const float* b_ih = (const float*)d_in[3];
    const float* b_hh = (const float*)d_in[4];
    float* out = (float*)d_out;

    cudaFuncSetAttribute(gi_mma,  cudaFuncAttributeMaxDynamicSharedMemorySize, SMEM_GIMMA);
    cudaFuncSetAttribute(gru_mma, cudaFuncAttributeMaxDynamicSharedMemorySize, SMEM_GRUMMA);

    gi_mma<<<148, 256, SMEM_GIMMA>>>(X, W_ih, b_ih, b_hh);
    gru_mma<<<BN/32, 512, SMEM_GRUMMA>>>(W_hh, b_hh, out);   // 325 CTAs x 2 groups x 16
}